// round 1
// baseline (speedup 1.0000x reference)
#include <cuda_runtime.h>

#define NB 2
#define HH 512
#define WW 512
#define MASK 511
#define HW (HH*WW)

#define TX 32          // tile cols = lanes
#define TY 4           // thread rows
#define RPT 4          // output rows per thread
#define TILE_H (TY*RPT)   // 16
#define YH (TILE_H+14)    // 30  (halo 7: |sy|<=5 + |dy|<=2)
#define YW (TX+14)        // 46
#define BH (TILE_H+10)    // 26  (halo 5)
#define BW (TX+10)        // 42

__device__ float g_y[NB*HW];   // luminance
__device__ float g_B[NB*HW];   // box5x5(y^2), circular

__device__ __forceinline__ float fsqrt_a(float x){ float y; asm("sqrt.approx.f32 %0, %1;" : "=f"(y) : "f"(x)); return y; }
__device__ __forceinline__ float fex2_a (float x){ float y; asm("ex2.approx.f32 %0, %1;"  : "=f"(y) : "f"(x)); return y; }
__device__ __forceinline__ float frcp_a (float x){ float y; asm("rcp.approx.f32 %0, %1;"  : "=f"(y) : "f"(x)); return y; }

// ---------------- Kernel 1: luminance of clipped x ----------------
__global__ void lum_kernel(const float* __restrict__ x){
    int idx = blockIdx.x*blockDim.x + threadIdx.x;
    if (idx >= NB*HW) return;
    int n  = idx >> 18;          // HW = 2^18
    int hw = idx & (HW-1);
    const float* xb = x + (size_t)n*3*HW;
    float r = __saturatef(xb[hw]);
    float g = __saturatef(xb[HW + hw]);
    float b = __saturatef(xb[2*HW + hw]);
    g_y[idx] = 0.299f*r + 0.587f*g + 0.114f*b;
}

// ---------------- Kernel 2: B = circular box5x5 of y^2 ----------------
__global__ void boxB_kernel(){
    int idx = blockIdx.x*blockDim.x + threadIdx.x;
    if (idx >= NB*HW) return;
    int n  = idx >> 18;
    int hw = idx & (HW-1);
    int h = hw >> 9, w = hw & MASK;
    const float* yb = g_y + n*HW;
    float acc = 0.f;
    #pragma unroll
    for (int dy=-2; dy<=2; ++dy){
        const float* row = yb + (((h+dy)&MASK) << 9);
        #pragma unroll
        for (int dx=-2; dx<=2; ++dx){
            float v = row[(w+dx)&MASK];
            acc = fmaf(v, v, acc);
        }
    }
    g_B[idx] = acc;
}

// ---------------- Kernel 3: main NLM ----------------
// D(p,s) = B(p) + B(p+s) - 2*C(p,s),  C = box5( y[.]*y[.+s] )
// C built via per-row 5-tap correlations (rc) + vertical sliding 5-row sum.
__global__ void __launch_bounds__(TX*TY) nlm_kernel(const float* __restrict__ x,
                                                    float* __restrict__ out){
    __shared__ float sY[YH][YW];
    __shared__ float sB[BH][BW];
    __shared__ float sX[3][BH][BW];

    const int n   = blockIdx.z;
    const int c0  = blockIdx.x * TX;
    const int r0  = blockIdx.y * TILE_H;
    const int tid = threadIdx.y*TX + threadIdx.x;

    const float* yb = g_y + n*HW;
    const float* Bb = g_B + n*HW;
    const float* xb = x + (size_t)n*3*HW;

    // cooperative loads with circular wrap
    for (int i = tid; i < YH*YW; i += TX*TY){
        int rr = i / YW, cc = i - rr*YW;
        sY[rr][cc] = yb[(((r0-7+rr)&MASK)<<9) | ((c0-7+cc)&MASK)];
    }
    for (int i = tid; i < BH*BW; i += TX*TY){
        int rr = i / BW, cc = i - rr*BW;
        int gi = (((r0-5+rr)&MASK)<<9) | ((c0-5+cc)&MASK);
        sB[rr][cc]    = Bb[gi];
        sX[0][rr][cc] = xb[gi];
        sX[1][rr][cc] = xb[HW + gi];
        sX[2][rr][cc] = xb[2*HW + gi];
    }
    __syncthreads();

    const int lane = threadIdx.x;       // col within tile
    const int trow = threadIdx.y * RPT; // first output row within tile

    float Bp[RPT], aw[RPT], a0[RPT], a1[RPT], a2[RPT];
    #pragma unroll
    for (int j=0;j<RPT;j++){
        Bp[j] = sB[trow+j+5][lane+5];
        aw[j]=0.f; a0[j]=0.f; a1[j]=0.f; a2[j]=0.f;
    }

    const float KEXP = -0.48089834696298783f;   // -1/(3*ln2)

    for (int sy=-5; sy<=5; ++sy){
        // rc rows i=0..7 correspond to tile rows trow-2+i -> sY row trow+i+5
        float ring[RPT][11];   // rc rows 0..3 (consumed only)
        float C[11];
        #pragma unroll
        for (int s=0;s<11;s++) C[s]=0.f;

        // warmup: rc rows 0..3
        #pragma unroll
        for (int i=0;i<RPT;i++){
            float cen[5], sh[15];
            #pragma unroll
            for (int k=0;k<5;k++)  cen[k] = sY[trow+i+5][lane+5+k];
            #pragma unroll
            for (int k=0;k<15;k++) sh[k]  = sY[trow+i+5+sy][lane+k];
            #pragma unroll
            for (int s=0;s<11;s++){
                float r = cen[0]*sh[s];
                r = fmaf(cen[1], sh[s+1], r);
                r = fmaf(cen[2], sh[s+2], r);
                r = fmaf(cen[3], sh[s+3], r);
                r = fmaf(cen[4], sh[s+4], r);
                ring[i][s] = r;
                C[s] += r;
            }
        }
        // main: emit output rows j=0..3 (rc row j+4 computed fresh each step)
        #pragma unroll
        for (int j=0;j<RPT;j++){
            float rcn[11];
            {
                float cen[5], sh[15];
                #pragma unroll
                for (int k=0;k<5;k++)  cen[k] = sY[trow+j+9][lane+5+k];
                #pragma unroll
                for (int k=0;k<15;k++) sh[k]  = sY[trow+j+9+sy][lane+k];
                #pragma unroll
                for (int s=0;s<11;s++){
                    float r = cen[0]*sh[s];
                    r = fmaf(cen[1], sh[s+1], r);
                    r = fmaf(cen[2], sh[s+2], r);
                    r = fmaf(cen[3], sh[s+3], r);
                    r = fmaf(cen[4], sh[s+4], r);
                    rcn[s] = r;
                }
            }
            #pragma unroll
            for (int s=0;s<11;s++) C[s] += rcn[s];   // C = rc rows j..j+4

            #pragma unroll
            for (int s=0;s<11;s++){
                float Bs = sB[trow+j+sy+5][lane+s];      // col = lane + (s-5) + 5
                float D  = fmaf(-2.f, C[s], Bp[j] + Bs);
                D = fmaxf(D, 0.f);
                float w = fex2_a(fsqrt_a(D) * KEXP);
                aw[j] += w;
                a0[j] = fmaf(w, sX[0][trow+j+sy+5][lane+s], a0[j]);
                a1[j] = fmaf(w, sX[1][trow+j+sy+5][lane+s], a1[j]);
                a2[j] = fmaf(w, sX[2][trow+j+sy+5][lane+s], a2[j]);
            }
            if (j < RPT-1){
                #pragma unroll
                for (int s=0;s<11;s++) C[s] -= ring[j][s];  // drop row j
            }
        }
    }

    #pragma unroll
    for (int j=0;j<RPT;j++){
        float rw = frcp_a(aw[j]);
        int gr = r0 + trow + j, gc = c0 + lane;
        size_t o = (size_t)n*3*HW + ((size_t)gr<<9) + gc;
        out[o]       = __saturatef(a0[j]*rw);
        out[o+HW]    = __saturatef(a1[j]*rw);
        out[o+2*HW]  = __saturatef(a2[j]*rw);
    }
}

extern "C" void kernel_launch(void* const* d_in, const int* in_sizes, int n_in,
                              void* d_out, int out_size){
    const float* x = (const float*)d_in[0];
    float* out = (float*)d_out;
    (void)in_sizes; (void)n_in; (void)out_size;

    lum_kernel <<<(NB*HW + 255)/256, 256>>>(x);
    boxB_kernel<<<(NB*HW + 255)/256, 256>>>();

    dim3 grid(WW/TX, HH/TILE_H, NB);   // 16 x 32 x 2
    dim3 block(TX, TY);                // 128 threads
    nlm_kernel<<<grid, block>>>(x, out);
}

// round 3
// speedup vs baseline: 1.4026x; 1.4026x over previous
#include <cuda_runtime.h>

#define NB 2
#define HH 512
#define WW 512
#define MASK 511
#define HW (HH*WW)

#define TXv 16          // lanes; each thread owns 2 adjacent columns
#define TYv 8
#define RPT 2
#define TILE_W 32       // 16 lanes * 2 cols
#define TILE_H 16       // 8 * RPT
#define YH 30           // TILE_H + 14 (halo 7 top/bottom)
#define YW 48           // TILE_W + 16 (halo 8 left, 8 right; even for LDS.64)
#define BH 26           // TILE_H + 10
#define BW 44           // TILE_W + 12 (halo 6/6, even)

typedef unsigned long long u64;

__device__ __forceinline__ float lo_(u64 v){ return __uint_as_float((unsigned)v); }
__device__ __forceinline__ float hi_(u64 v){ return __uint_as_float((unsigned)(v >> 32)); }
__device__ __forceinline__ u64 pk_(float a, float b){ u64 r; asm("mov.b64 %0, {%1, %2};" : "=l"(r) : "f"(a), "f"(b)); return r; }
__device__ __forceinline__ u64 fma2_(u64 a, u64 b, u64 c){ u64 d; asm("fma.rn.f32x2 %0, %1, %2, %3;" : "=l"(d) : "l"(a), "l"(b), "l"(c)); return d; }
__device__ __forceinline__ u64 add2_(u64 a, u64 b){ u64 d; asm("add.rn.f32x2 %0, %1, %2;" : "=l"(d) : "l"(a), "l"(b)); return d; }
__device__ __forceinline__ u64 mul2_(u64 a, u64 b){ u64 d; asm("mul.rn.f32x2 %0, %1, %2;" : "=l"(d) : "l"(a), "l"(b)); return d; }
__device__ __forceinline__ float fsqrt_a(float x){ float y; asm("sqrt.approx.f32 %0, %1;" : "=f"(y) : "f"(x)); return y; }
__device__ __forceinline__ float fex2_a (float x){ float y; asm("ex2.approx.f32 %0, %1;"  : "=f"(y) : "f"(x)); return y; }
__device__ __forceinline__ float frcp_a (float x){ float y; asm("rcp.approx.f32 %0, %1;"  : "=f"(y) : "f"(x)); return y; }

#define NEG2_2 0xC0000000C0000000ULL   // {-2.f, -2.f}
#define NEG1_2 0xBF800000BF800000ULL   // {-1.f, -1.f}

__global__ void __launch_bounds__(TXv*TYv) nlm_kernel(const float* __restrict__ x,
                                                      float* __restrict__ out){
    __shared__ float sX[3][YH][YW];   // raw x, halo 8/7
    __shared__ float sY[YH][YW];      // clipped luminance
    __shared__ float sH[YH][BW];      // horizontal box5 of y^2
    __shared__ float sB[BH][BW];      // full box5x5 of y^2

    const int n   = blockIdx.z;
    const int c0  = blockIdx.x * TILE_W;
    const int r0  = blockIdx.y * TILE_H;
    const int tid = threadIdx.y * TXv + threadIdx.x;
    const float* xb = x + (size_t)n*3*HW;

    // ---- load x tile (raw) + compute clipped luminance ----
    for (int i = tid; i < YH*YW; i += TXv*TYv){
        int rr = i / YW, cc = i - rr*YW;
        int gi = (((r0-7+rr)&MASK) << 9) | ((c0-8+cc)&MASK);
        float v0 = xb[gi], v1 = xb[HW+gi], v2 = xb[2*HW+gi];
        sX[0][rr][cc] = v0; sX[1][rr][cc] = v1; sX[2][rr][cc] = v2;
        sY[rr][cc] = 0.299f*__saturatef(v0) + 0.587f*__saturatef(v1) + 0.114f*__saturatef(v2);
    }
    __syncthreads();
    // ---- horizontal box5 of y^2 : sH[r][cc] centered at global col c0-6+cc ----
    for (int i = tid; i < YH*BW; i += TXv*TYv){
        int rr = i / BW, cc = i - rr*BW;
        float a = 0.f;
        #pragma unroll
        for (int u = 0; u < 5; u++){ float v = sY[rr][cc+u]; a = fmaf(v, v, a); }
        sH[rr][cc] = a;
    }
    __syncthreads();
    // ---- vertical box5 : sB[rb] centered at global row r0-5+rb ----
    for (int i = tid; i < BH*BW; i += TXv*TYv){
        int rr = i / BW, cc = i - rr*BW;
        sB[rr][cc] = sH[rr][cc] + sH[rr+1][cc] + sH[rr+2][cc] + sH[rr+3][cc] + sH[rr+4][cc];
    }
    __syncthreads();

    const int lx   = threadIdx.x;
    const int trow = threadIdx.y * RPT;
    const int col2 = 2*lx;                 // tile-relative even column
    const float KEXP = -0.48089834696298783f;   // -1/(3*ln2)

    u64 Bp2[RPT];
    #pragma unroll
    for (int j = 0; j < RPT; j++)
        Bp2[j] = *(const u64*)&sB[trow+j+5][col2+6];

    u64 aw2[RPT], a02[RPT], a12[RPT], a22[RPT];
    #pragma unroll
    for (int j = 0; j < RPT; j++){ aw2[j]=0; a02[j]=0; a12[j]=0; a22[j]=0; }

    // packed row correlation: rc2[s] = { rc(col c, sx=s-5), rc(col c+1, sx=s-5) }
    auto rc_row = [&](int cenr, int shr, u64* rc){
        u64 T[9], U[3];
        #pragma unroll
        for (int i = 0; i < 9; i++) T[i] = *(const u64*)&sY[shr][col2 + 2*i];
        #pragma unroll
        for (int t = 0; t < 3; t++) U[t] = *(const u64*)&sY[cenr][col2 + 6 + 2*t];
        u64 cen2[5];
        cen2[0] = U[0]; cen2[2] = U[1]; cen2[4] = U[2];
        cen2[1] = pk_(hi_(U[0]), lo_(U[1]));
        cen2[3] = pk_(hi_(U[1]), lo_(U[2]));
        u64 sh2[15];
        #pragma unroll
        for (int q = 1; q <= 15; q++)
            sh2[q-1] = (q & 1) ? pk_(hi_(T[(q-1)>>1]), lo_(T[(q+1)>>1])) : T[q>>1];
        #pragma unroll
        for (int s = 0; s < 11; s++){
            u64 r = mul2_(cen2[0], sh2[s]);
            r = fma2_(cen2[1], sh2[s+1], r);
            r = fma2_(cen2[2], sh2[s+2], r);
            r = fma2_(cen2[3], sh2[s+3], r);
            r = fma2_(cen2[4], sh2[s+4], r);
            rc[s] = r;
        }
    };

    #pragma unroll 1
    for (int sy = -5; sy <= 5; ++sy){
        u64 C2[11], ring2[11];
        // warm-up: rc rows for template rows trow-2 .. trow+2
        {
            u64 rc[11];
            rc_row(trow+5, trow+5+sy, rc);
            #pragma unroll
            for (int s = 0; s < 11; s++){ ring2[s] = rc[s]; C2[s] = rc[s]; }
        }
        #pragma unroll
        for (int m = 1; m < 5; m++){
            u64 rc[11];
            rc_row(trow+m+5, trow+m+5+sy, rc);
            #pragma unroll
            for (int s = 0; s < 11; s++) C2[s] = add2_(C2[s], rc[s]);
        }

        #pragma unroll
        for (int j = 0; j < RPT; j++){
            if (j == 1){
                u64 rc[11];
                rc_row(trow+10, trow+10+sy, rc);
                #pragma unroll
                for (int s = 0; s < 11; s++){
                    C2[s] = add2_(C2[s], rc[s]);
                    C2[s] = fma2_(ring2[s], NEG1_2, C2[s]);   // subtract oldest row
                }
            }
            const int br = trow + j + sy + 5;   // sB row
            const int xr = trow + j + sy + 7;   // sX/sY-space row

            u64 V[7];
            #pragma unroll
            for (int i = 0; i < 7; i++) V[i] = *(const u64*)&sB[br][col2 + 2*i];

            u64 w2[11];
            #pragma unroll
            for (int s = 0; s < 11; s++){
                u64 Bs2 = (s & 1) ? V[(s+1)>>1] : pk_(hi_(V[s>>1]), lo_(V[(s>>1)+1]));
                u64 D2  = fma2_(C2[s], NEG2_2, add2_(Bp2[j], Bs2));
                float d0 = fmaxf(lo_(D2), 0.f);
                float d1 = fmaxf(hi_(D2), 0.f);
                float w0 = fex2_a(fsqrt_a(d0) * KEXP);
                float w1 = fex2_a(fsqrt_a(d1) * KEXP);
                u64 w = pk_(w0, w1);
                w2[s] = w;
                aw2[j] = add2_(aw2[j], w);
            }
            #pragma unroll
            for (int ch = 0; ch < 3; ch++){
                u64 W_[8];
                #pragma unroll
                for (int i = 1; i < 8; i++) W_[i] = *(const u64*)&sX[ch][xr][col2 + 2*i];
                u64 acc = (ch==0) ? a02[j] : (ch==1) ? a12[j] : a22[j];
                #pragma unroll
                for (int s = 0; s < 11; s++){
                    u64 x2 = (s & 1) ? W_[(s+3)>>1] : pk_(hi_(W_[(s+2)>>1]), lo_(W_[(s+4)>>1]));
                    acc = fma2_(w2[s], x2, acc);
                }
                if (ch==0) a02[j] = acc; else if (ch==1) a12[j] = acc; else a22[j] = acc;
            }
        }
    }

    // ---- epilogue ----
    #pragma unroll
    for (int j = 0; j < RPT; j++){
        float rw0 = frcp_a(lo_(aw2[j]));
        float rw1 = frcp_a(hi_(aw2[j]));
        int gr = r0 + trow + j;
        int gc = c0 + col2;
        size_t o = (size_t)n*3*HW + ((size_t)gr << 9) + gc;
        float2 o0 = make_float2(__saturatef(lo_(a02[j])*rw0), __saturatef(hi_(a02[j])*rw1));
        float2 o1 = make_float2(__saturatef(lo_(a12[j])*rw0), __saturatef(hi_(a12[j])*rw1));
        float2 o2 = make_float2(__saturatef(lo_(a22[j])*rw0), __saturatef(hi_(a22[j])*rw1));
        *(float2*)&out[o]        = o0;
        *(float2*)&out[o + HW]   = o1;
        *(float2*)&out[o + 2*HW] = o2;
    }
}

extern "C" void kernel_launch(void* const* d_in, const int* in_sizes, int n_in,
                              void* d_out, int out_size){
    const float* x = (const float*)d_in[0];
    float* out = (float*)d_out;
    (void)in_sizes; (void)n_in; (void)out_size;

    dim3 grid(WW/TILE_W, HH/TILE_H, NB);   // 16 x 32 x 2
    dim3 block(TXv, TYv);                  // 128 threads
    nlm_kernel<<<grid, block>>>(x, out);
}

// round 6
// speedup vs baseline: 1.6221x; 1.1565x over previous
#include <cuda_runtime.h>

#define NB 2
#define HH 512
#define WW 512
#define MASK 511
#define HW (HH*WW)

#define LANES 16        // threads per row; thread owns cols (c, c+16)
#define TYv 8
#define RPT 2
#define TILE_W 32
#define TILE_H 16       // TYv * RPT

#define RC_ROWS 20      // template rows -2..17
#define YP_ROWS 30      // y rows -7..22
#define YP_COLS 30      // y col-pair index: logical col -7..22 (.x), +16 (.y)
#define BP_ROWS 26      // B/x rows -5..20
#define BP_COLS 26      // col-pair index: logical col -5..20 (.x), +16 (.y)

// offsets in u64 (=float2) units
#define OFF_RC 0
#define OFF_YP (RC_ROWS*11*LANES)              // 3520
#define OFF_BP (OFF_YP + YP_ROWS*YP_COLS)      // 4420
#define OFF_XP (OFF_BP + BP_ROWS*BP_COLS)      // 5096
#define SMEM_U64 (OFF_XP + 3*BP_ROWS*BP_COLS)  // 7124
#define SMEM_BYTES (SMEM_U64*8)                // 56992

typedef unsigned long long u64;

__device__ __forceinline__ float lo_(u64 v){ return __uint_as_float((unsigned)v); }
__device__ __forceinline__ float hi_(u64 v){ return __uint_as_float((unsigned)(v >> 32)); }
__device__ __forceinline__ u64 pk_(float a, float b){ u64 r; asm("mov.b64 %0, {%1, %2};" : "=l"(r) : "f"(a), "f"(b)); return r; }
__device__ __forceinline__ u64 fma2_(u64 a, u64 b, u64 c){ u64 d; asm("fma.rn.f32x2 %0, %1, %2, %3;" : "=l"(d) : "l"(a), "l"(b), "l"(c)); return d; }
__device__ __forceinline__ u64 add2_(u64 a, u64 b){ u64 d; asm("add.rn.f32x2 %0, %1, %2;" : "=l"(d) : "l"(a), "l"(b)); return d; }
__device__ __forceinline__ u64 mul2_(u64 a, u64 b){ u64 d; asm("mul.rn.f32x2 %0, %1, %2;" : "=l"(d) : "l"(a), "l"(b)); return d; }
__device__ __forceinline__ float fsqrt_a(float x){ float y; asm("sqrt.approx.f32 %0, %1;" : "=f"(y) : "f"(x)); return y; }
__device__ __forceinline__ float fex2_a (float x){ float y; asm("ex2.approx.f32 %0, %1;"  : "=f"(y) : "f"(x)); return y; }
__device__ __forceinline__ float frcp_a (float x){ float y; asm("rcp.approx.f32 %0, %1;"  : "=f"(y) : "f"(x)); return y; }

#define NEG2_2 0xC0000000C0000000ULL   // {-2.f, -2.f}
#define NEG1_2 0xBF800000BF800000ULL   // {-1.f, -1.f}

__global__ void __launch_bounds__(LANES*TYv, 3) nlm_kernel(const float* __restrict__ x,
                                                           float* __restrict__ out){
    extern __shared__ u64 smem[];
    u64* rcS = smem + OFF_RC;     // [rr][s][lane]
    u64* sYp = smem + OFF_YP;     // [r][jj]
    u64* sBp = smem + OFF_BP;     // [rb][jj]
    u64* sXp = smem + OFF_XP;     // [ch][rb][jj]
    u64* sHp = smem + OFF_RC;     // alias: transient hbox(y^2), [r][jj] 30x26

    const int n   = blockIdx.z;
    const int c0  = blockIdx.x * TILE_W;
    const int r0  = blockIdx.y * TILE_H;
    const int tid = threadIdx.y * LANES + threadIdx.x;
    const float* xb = x + (size_t)n*3*HW;

    // ---- sYp: packed clipped luminance, pair {col, col+16} ----
    for (int i = tid; i < YP_ROWS*YP_COLS; i += LANES*TYv){
        int r = i / YP_COLS, jj = i - r*YP_COLS;
        int base = ((r0 + r - 7) & MASK) << 9;
        int gx = base | ((c0 + jj - 7) & MASK);
        int gy = base | ((c0 + jj + 9) & MASK);
        float l0 = 0.299f*__saturatef(xb[gx]) + 0.587f*__saturatef(xb[HW+gx]) + 0.114f*__saturatef(xb[2*HW+gx]);
        float l1 = 0.299f*__saturatef(xb[gy]) + 0.587f*__saturatef(xb[HW+gy]) + 0.114f*__saturatef(xb[2*HW+gy]);
        sYp[i] = pk_(l0, l1);
    }
    __syncthreads();
    // ---- sHp: horizontal box5 of y^2 (packed) ----
    for (int i = tid; i < YP_ROWS*BP_COLS; i += LANES*TYv){
        int r = i / BP_COLS, jj = i - r*BP_COLS;
        const u64* p = &sYp[r*YP_COLS + jj];
        u64 a = mul2_(p[0], p[0]);
        a = fma2_(p[1], p[1], a);
        a = fma2_(p[2], p[2], a);
        a = fma2_(p[3], p[3], a);
        a = fma2_(p[4], p[4], a);
        sHp[r*BP_COLS + jj] = a;
    }
    __syncthreads();
    // ---- sBp: vertical box5 of sHp ; sXp: packed raw x ----
    for (int i = tid; i < BP_ROWS*BP_COLS; i += LANES*TYv){
        int rb = i / BP_COLS, jj = i - rb*BP_COLS;
        const u64* p = &sHp[rb*BP_COLS + jj];
        sBp[i] = add2_(add2_(add2_(p[0], p[BP_COLS]), add2_(p[2*BP_COLS], p[3*BP_COLS])), p[4*BP_COLS]);
        int base = ((r0 + rb - 5) & MASK) << 9;
        int gx = base | ((c0 + jj - 5) & MASK);
        int gy = base | ((c0 + jj + 11) & MASK);
        sXp[i]                     = pk_(xb[gx],      xb[gy]);
        sXp[BP_ROWS*BP_COLS + i]   = pk_(xb[HW+gx],   xb[HW+gy]);
        sXp[2*BP_ROWS*BP_COLS + i] = pk_(xb[2*HW+gx], xb[2*HW+gy]);
    }
    __syncthreads();

    const int lx   = threadIdx.x;
    const int trow = threadIdx.y * RPT;
    const float KEXP = -0.48089834696298783f;   // -1/(3*ln2)

    u64 Bp2[RPT];
    #pragma unroll
    for (int j = 0; j < RPT; j++)
        Bp2[j] = sBp[(trow+j+5)*BP_COLS + lx + 5];

    u64 aw2[RPT], a02[RPT], a12[RPT], a22[RPT];
    #pragma unroll
    for (int j = 0; j < RPT; j++){ aw2[j]=0; a02[j]=0; a12[j]=0; a22[j]=0; }

    #pragma unroll 1
    for (int sy = -5; sy <= 5; ++sy){
        // ---- Phase A: cooperative row correlations into rcS ----
        // rc(rr, s, lane) for template row rr-2, shift (sy, s-5), col pair (lane, lane+16)
        for (int t = tid; t < RC_ROWS*LANES; t += LANES*TYv){
            int rr = t / LANES, cl = t - rr*LANES;
            const u64* cenp = &sYp[(rr+5)*YP_COLS + cl + 5];
            const u64* shp  = &sYp[(rr+5+sy)*YP_COLS + cl];
            u64 cen[5], sh[15];
            #pragma unroll
            for (int k = 0; k < 5; k++)  cen[k] = cenp[k];
            #pragma unroll
            for (int q = 0; q < 15; q++) sh[q]  = shp[q];
            u64* dst = &rcS[rr*11*LANES + cl];
            #pragma unroll
            for (int s = 0; s < 11; s++){
                u64 r = mul2_(cen[0], sh[s]);
                r = fma2_(cen[1], sh[s+1], r);
                r = fma2_(cen[2], sh[s+2], r);
                r = fma2_(cen[3], sh[s+3], r);
                r = fma2_(cen[4], sh[s+4], r);
                dst[s*LANES] = r;
            }
        }
        __syncthreads();

        // ---- Phase B: sliding C window + weights + accumulation ----
        u64 C2[11];
        {
            const u64* p = &rcS[trow*11*LANES + lx];
            #pragma unroll
            for (int s = 0; s < 11; s++){
                u64 c = add2_(p[s*LANES], p[(11+s)*LANES]);
                c = add2_(c, p[(22+s)*LANES]);
                c = add2_(c, p[(33+s)*LANES]);
                C2[s] = add2_(c, p[(44+s)*LANES]);
            }
        }
        #pragma unroll
        for (int j = 0; j < RPT; j++){
            if (j == 1){
                const u64* pn = &rcS[(trow+5)*11*LANES + lx];
                const u64* po = &rcS[trow*11*LANES + lx];
                #pragma unroll
                for (int s = 0; s < 11; s++)
                    C2[s] = fma2_(po[s*LANES], NEG1_2, add2_(C2[s], pn[s*LANES]));
            }
            const int br = trow + j + sy + 5;
            const u64* Brow = &sBp[br*BP_COLS + lx];
            u64 w2[11];
            #pragma unroll
            for (int s = 0; s < 11; s++){
                u64 D2 = fma2_(C2[s], NEG2_2, add2_(Bp2[j], Brow[s]));
                float d0 = fmaxf(lo_(D2), 0.f);
                float d1 = fmaxf(hi_(D2), 0.f);
                float w0 = fex2_a(fsqrt_a(d0) * KEXP);
                float w1 = fex2_a(fsqrt_a(d1) * KEXP);
                u64 w = pk_(w0, w1);
                w2[s] = w;
                aw2[j] = add2_(aw2[j], w);
            }
            #pragma unroll
            for (int ch = 0; ch < 3; ch++){
                const u64* Xrow = &sXp[(ch*BP_ROWS + br)*BP_COLS + lx];
                u64 acc = (ch==0) ? a02[j] : (ch==1) ? a12[j] : a22[j];
                #pragma unroll
                for (int s = 0; s < 11; s++)
                    acc = fma2_(w2[s], Xrow[s], acc);
                if (ch==0) a02[j] = acc; else if (ch==1) a12[j] = acc; else a22[j] = acc;
            }
        }
        __syncthreads();   // rcS reused next sy
    }

    // ---- epilogue: columns (c0+lx, c0+lx+16) ----
    #pragma unroll
    for (int j = 0; j < RPT; j++){
        float rw0 = frcp_a(lo_(aw2[j]));
        float rw1 = frcp_a(hi_(aw2[j]));
        int gr = r0 + trow + j;
        size_t o = (size_t)n*3*HW + ((size_t)gr << 9) + c0 + lx;
        out[o]           = __saturatef(lo_(a02[j])*rw0);
        out[o+16]        = __saturatef(hi_(a02[j])*rw1);
        out[o+HW]        = __saturatef(lo_(a12[j])*rw0);
        out[o+HW+16]     = __saturatef(hi_(a12[j])*rw1);
        out[o+2*HW]      = __saturatef(lo_(a22[j])*rw0);
        out[o+2*HW+16]   = __saturatef(hi_(a22[j])*rw1);
    }
}

extern "C" void kernel_launch(void* const* d_in, const int* in_sizes, int n_in,
                              void* d_out, int out_size){
    const float* x = (const float*)d_in[0];
    float* out = (float*)d_out;
    (void)in_sizes; (void)n_in; (void)out_size;

    cudaFuncSetAttribute(nlm_kernel, cudaFuncAttributeMaxDynamicSharedMemorySize, SMEM_BYTES);

    dim3 grid(WW/TILE_W, HH/TILE_H, NB);   // 16 x 32 x 2
    dim3 block(LANES, TYv);                // 128 threads
    nlm_kernel<<<grid, block, SMEM_BYTES>>>(x, out);
}